// round 14
// baseline (speedup 1.0000x reference)
#include <cuda_runtime.h>
#include <cuda_bf16.h>
#include <math.h>
#include <cstdint>

#define Bn 8
#define Tn 96
#define Sn 192
#define Dn 512
#define BT (Bn*Tn)   // 768
#define BS (Bn*Sn)   // 1536

// fp32 scratch
__device__ float g_wq  [BT * Dn];
__device__ float g_uh  [BS * Dn];
__device__ float g_wm  [BS * Dn];
__device__ float g_base[BT * Dn];
__device__ float g_p   [BT * Sn];

// bf16 hi/lo pre-converted operands
__device__ __nv_bfloat16 g_in_h [BT * Dn],  g_in_l [BT * Dn];
__device__ __nv_bfloat16 g_mem_h[BS * Dn],  g_mem_l[BS * Dn];
__device__ __nv_bfloat16 g_wqw_h[Dn * Dn],  g_wqw_l[Dn * Dn];
__device__ __nv_bfloat16 g_wcw_h[Dn * Dn],  g_wcw_l[Dn * Dn];
__device__ __nv_bfloat16 g_wow_h[Dn * 1024], g_wow_l[Dn * 1024];

__device__ __forceinline__ float tanh_fast(float x) {
    float y;
    asm("tanh.approx.f32 %0, %1;" : "=f"(y) : "f"(x));
    return y;
}
__device__ __forceinline__ uint32_t smem_u32(const void* p) {
    uint32_t a;
    asm("{ .reg .u64 t; cvta.to.shared.u64 t, %1; cvt.u32.u64 %0, t; }" : "=r"(a) : "l"(p));
    return a;
}
__device__ __forceinline__ void ldsm4(uint32_t* r, uint32_t addr) {
    asm volatile("ldmatrix.sync.aligned.m8n8.x4.shared.b16 {%0,%1,%2,%3}, [%4];"
        : "=r"(r[0]), "=r"(r[1]), "=r"(r[2]), "=r"(r[3]) : "r"(addr));
}
__device__ __forceinline__ void ldsm2(uint32_t* r, uint32_t addr) {
    asm volatile("ldmatrix.sync.aligned.m8n8.x2.shared.b16 {%0,%1}, [%2];"
        : "=r"(r[0]), "=r"(r[1]) : "r"(addr));
}
__device__ __forceinline__ void mma16816(float* c, const uint32_t* a, const uint32_t* b) {
    asm volatile(
        "mma.sync.aligned.m16n8k16.row.col.f32.bf16.bf16.f32 "
        "{%0,%1,%2,%3}, {%4,%5,%6,%7}, {%8,%9}, {%0,%1,%2,%3};"
        : "+f"(c[0]), "+f"(c[1]), "+f"(c[2]), "+f"(c[3])
        : "r"(a[0]), "r"(a[1]), "r"(a[2]), "r"(a[3]), "r"(b[0]), "r"(b[1]));
}
__device__ __forceinline__ void cp16(uint32_t dst, const void* src) {
    asm volatile("cp.async.cg.shared.global [%0], [%1], 16;" :: "r"(dst), "l"(src));
}

// ----------------------------------------------------------------------------
// Stage 0: fp32 -> bf16 hi/lo pre-conversion. One float4 per thread.
// Segments (float4 units): in 98304 | mem 196608 | Wq 65536 | Wc 65536 | Wout 131072
// Grid 2176 x 256 = 557056 exactly.
// ----------------------------------------------------------------------------
__global__ void __launch_bounds__(256) preconvert(
    const float4* __restrict__ inputs, const float4* __restrict__ mems,
    const float4* __restrict__ Wq, const float4* __restrict__ Wc,
    const float4* __restrict__ Wout,
    __nv_bfloat16* in_h, __nv_bfloat16* in_l,
    __nv_bfloat16* mem_h, __nv_bfloat16* mem_l,
    __nv_bfloat16* wq_h, __nv_bfloat16* wq_l,
    __nv_bfloat16* wc_h, __nv_bfloat16* wc_l,
    __nv_bfloat16* wo_h, __nv_bfloat16* wo_l)
{
    int idx = blockIdx.x * 256 + threadIdx.x;
    const float4* src; __nv_bfloat16 *hp, *lp; int e;
    if (idx < 98304)       { src = inputs; e = idx;          hp = in_h;  lp = in_l;  }
    else if (idx < 294912) { src = mems;   e = idx - 98304;  hp = mem_h; lp = mem_l; }
    else if (idx < 360448) { src = Wq;     e = idx - 294912; hp = wq_h;  lp = wq_l;  }
    else if (idx < 425984) { src = Wc;     e = idx - 360448; hp = wc_h;  lp = wc_l;  }
    else                   { src = Wout;   e = idx - 425984; hp = wo_h;  lp = wo_l;  }
    float4 f = src[e];
    __nv_bfloat162 h01 = __float22bfloat162_rn(make_float2(f.x, f.y));
    __nv_bfloat162 h23 = __float22bfloat162_rn(make_float2(f.z, f.w));
    float2 g01 = __bfloat1622float2(h01);
    float2 g23 = __bfloat1622float2(h23);
    __nv_bfloat162 l01 = __float22bfloat162_rn(make_float2(f.x - g01.x, f.y - g01.y));
    __nv_bfloat162 l23 = __float22bfloat162_rn(make_float2(f.z - g23.x, f.w - g23.y));
    uint2 hv = make_uint2(*(uint32_t*)&h01, *(uint32_t*)&h23);
    uint2 lv = make_uint2(*(uint32_t*)&l01, *(uint32_t*)&l23);
    *(uint2*)(hp + (size_t)e * 4) = hv;
    *(uint2*)(lp + (size_t)e * 4) = lv;
}

// ----------------------------------------------------------------------------
// Stage 1: mma.sync bf16 hi/lo (3 terms), sources pre-converted in gmem,
// staged via cp.async. CTA tile 128x128, 512 thr = 16 warps (4Mx4N),
// warp tile 32x32, K-chunk 32, 2-stage cp.async pipeline, 1 barrier/chunk.
// Grid (4, 36) = 144 CTAs = one wave.
// ----------------------------------------------------------------------------
#define PITCH 80
#define BUFB 40960
#define S1_SMEM (2 * BUFB)   // 81920

__global__ void __launch_bounds__(512, 1) stage1_mma(
    const __nv_bfloat16* __restrict__ in_h, const __nv_bfloat16* __restrict__ in_l,
    const __nv_bfloat16* __restrict__ mem_h, const __nv_bfloat16* __restrict__ mem_l,
    const __nv_bfloat16* __restrict__ wqw_h, const __nv_bfloat16* __restrict__ wqw_l,
    const __nv_bfloat16* __restrict__ wcw_h, const __nv_bfloat16* __restrict__ wcw_l,
    const __nv_bfloat16* __restrict__ wow_h, const __nv_bfloat16* __restrict__ wow_l,
    const float* __restrict__ bc, const float* __restrict__ bout,
    float* __restrict__ wq_o, float* __restrict__ uh_o,
    float* __restrict__ wm_o, float* __restrict__ base_o)
{
    extern __shared__ __align__(16) unsigned char smem[];
    const uint32_t sb = smem_u32(smem);

    const int y = blockIdx.y;
    const __nv_bfloat16 *aH, *aL, *wH, *wL;
    int ldw; const float* bias; float* C; int row0;
    if (y < 6)       { aH = in_h;  aL = in_l;  wH = wqw_h;       wL = wqw_l;       ldw = 512;  bias = nullptr; C = wq_o;   row0 = y * 128; }
    else if (y < 18) { aH = mem_h; aL = mem_l; wH = wcw_h;       wL = wcw_l;       ldw = 512;  bias = bc;      C = uh_o;   row0 = (y-6)*128; }
    else if (y < 30) { aH = mem_h; aL = mem_l; wH = wow_h;       wL = wow_l;       ldw = 1024; bias = nullptr; C = wm_o;   row0 = (y-18)*128; }
    else             { aH = in_h;  aL = in_l;  wH = wow_h + 512; wL = wow_l + 512; ldw = 1024; bias = bout;    C = base_o; row0 = (y-30)*128; }
    const int col0 = blockIdx.x * 128;

    const int tid  = threadIdx.x;
    const int wid  = tid >> 5;
    const int lane = tid & 31;
    const int wM   = wid >> 2;
    const int wN   = wid & 3;

    // cp.async mapping: sec 0=Ah 1=Al 2=Bh 3=Bl, one 64B row-chunk per thread
    const int sec = tid >> 7;
    const int row = tid & 127;
    const __nv_bfloat16* csrc;
    if      (sec == 0) csrc = aH + (size_t)(row0 + row) * Dn;
    else if (sec == 1) csrc = aL + (size_t)(row0 + row) * Dn;
    else if (sec == 2) csrc = wH + (size_t)(col0 + row) * ldw;
    else               csrc = wL + (size_t)(col0 + row) * ldw;
    const uint32_t dstOff = (uint32_t)(sec * 10240 + row * PITCH);

    // ldmatrix per-warp offsets (relative to buffer base; section offsets 0/10240/20480/30720)
    const uint32_t aOffA = (uint32_t)((wM * 32 + (lane & 15)) * PITCH + ((lane >> 4) << 4));
    const uint32_t aOffB = (uint32_t)((wN * 32 + (lane & 7)) * PITCH + (((lane >> 3) & 1) << 4));

    float acc[2][4][4];
    #pragma unroll
    for (int i = 0; i < 2; i++)
        #pragma unroll
        for (int j = 0; j < 4; j++)
            #pragma unroll
            for (int q = 0; q < 4; q++) acc[i][j][q] = 0.f;

    // prologue: stage chunks 0 and 1
    {
        const char* s0 = (const char*)csrc;
        uint32_t d0 = sb + dstOff;
        cp16(d0, s0); cp16(d0 + 16, s0 + 16); cp16(d0 + 32, s0 + 32); cp16(d0 + 48, s0 + 48);
        asm volatile("cp.async.commit_group;");
        const char* s1 = (const char*)csrc + 64;
        uint32_t d1 = sb + BUFB + dstOff;
        cp16(d1, s1); cp16(d1 + 16, s1 + 16); cp16(d1 + 32, s1 + 32); cp16(d1 + 48, s1 + 48);
        asm volatile("cp.async.commit_group;");
        asm volatile("cp.async.wait_group 1;");
    }
    __syncthreads();

    for (int c = 0; c < 16; c++) {
        const uint32_t bufc = sb + (uint32_t)((c & 1) * BUFB);

        // ---- MMA on current buffer: 2 k16-steps x 3 terms ----
        #pragma unroll
        for (int ks = 0; ks < 2; ks++) {
            const uint32_t kb = (uint32_t)(ks * 32);
            uint32_t Ah[2][4], Bh[4][2];
            #pragma unroll
            for (int mi = 0; mi < 2; mi++)
                ldsm4(Ah[mi], bufc + aOffA + mi * (16 * PITCH) + kb);
            #pragma unroll
            for (int ni = 0; ni < 4; ni++)
                ldsm2(Bh[ni], bufc + 20480 + aOffB + ni * (8 * PITCH) + kb);
            #pragma unroll
            for (int mi = 0; mi < 2; mi++)
                #pragma unroll
                for (int ni = 0; ni < 4; ni++)
                    mma16816(acc[mi][ni], Ah[mi], Bh[ni]);

            uint32_t Al[2][4];
            #pragma unroll
            for (int mi = 0; mi < 2; mi++)
                ldsm4(Al[mi], bufc + 10240 + aOffA + mi * (16 * PITCH) + kb);
            #pragma unroll
            for (int mi = 0; mi < 2; mi++)
                #pragma unroll
                for (int ni = 0; ni < 4; ni++)
                    mma16816(acc[mi][ni], Al[mi], Bh[ni]);

            uint32_t Bl[4][2];
            #pragma unroll
            for (int ni = 0; ni < 4; ni++)
                ldsm2(Bl[ni], bufc + 30720 + aOffB + ni * (8 * PITCH) + kb);
            #pragma unroll
            for (int mi = 0; mi < 2; mi++)
                #pragma unroll
                for (int ni = 0; ni < 4; ni++)
                    mma16816(acc[mi][ni], Ah[mi], Bl[ni]);
        }
        __syncthreads();

        // ---- prefetch chunk c+2 into the buffer just consumed ----
        if (c + 2 < 16) {
            const char* s = (const char*)csrc + (c + 2) * 64;
            uint32_t d = sb + (uint32_t)((c & 1) * BUFB) + dstOff;
            cp16(d, s); cp16(d + 16, s + 16); cp16(d + 32, s + 32); cp16(d + 48, s + 48);
            asm volatile("cp.async.commit_group;");
            asm volatile("cp.async.wait_group 1;");   // chunk c+1 landed
        } else {
            asm volatile("cp.async.wait_group 0;");   // drain tail
        }
    }

    // ---- epilogue ----
    const int erow = lane >> 2;
    const int ecol = (lane & 3) * 2;
    #pragma unroll
    for (int mi = 0; mi < 2; mi++) {
        const int r0 = row0 + wM * 32 + mi * 16 + erow;
        #pragma unroll
        for (int ni = 0; ni < 4; ni++) {
            const int cc = col0 + wN * 32 + ni * 8 + ecol;
            float b0 = 0.f, b1 = 0.f;
            if (bias) { b0 = bias[cc]; b1 = bias[cc + 1]; }
            float2 o0 = make_float2(acc[mi][ni][0] + b0, acc[mi][ni][1] + b1);
            float2 o1 = make_float2(acc[mi][ni][2] + b0, acc[mi][ni][3] + b1);
            *(float2*)(C + (size_t)r0 * Dn + cc)       = o0;
            *(float2*)(C + (size_t)(r0 + 8) * Dn + cc) = o1;
        }
    }
}

// ----------------------------------------------------------------------------
// Stage 2: fused score + masked softmax (exact R10 version, 256 thr).
// ----------------------------------------------------------------------------
__global__ void __launch_bounds__(256) score_softmax(
    const float* __restrict__ wq, const float* __restrict__ uh,
    const float* __restrict__ v, const int* __restrict__ lens,
    float* __restrict__ P, float* __restrict__ out_align, int write_align)
{
    const int t0 = blockIdx.x * 4;
    const int b  = blockIdx.y;
    const int tid = threadIdx.x, w = tid >> 5, lane = tid & 31;
    const int tloc = w >> 1;
    const int sh   = w & 1;
    const int sbas = sh * 96 + lane;

    __shared__ __align__(16) float wq_sh[4][Dn];
    __shared__ __align__(16) float v_sh[Dn];
    __shared__ __align__(16) float uh_sh[Sn][36];
    __shared__ float rmax[8], rsum[8];

    for (int i = tid; i < 4 * (Dn/4); i += 256) {
        int t = i >> 7, j = i & 127;
        ((float4*)wq_sh[t])[j] = ((const float4*)(wq + ((size_t)(b*Tn + t0 + t)) * Dn))[j];
    }
    for (int i = tid; i < Dn/4; i += 256)
        ((float4*)v_sh)[i] = ((const float4*)v)[i];

    float a0=0.f, a1=0.f, a2=0.f;

    for (int m0 = 0; m0 < Dn; m0 += 32) {
        __syncthreads();
        #pragma unroll
        for (int i = tid; i < Sn * 8; i += 256) {
            int row = i >> 3, mm = (i & 7) << 2;
            *(float4*)&uh_sh[row][mm] =
                *(const float4*)(uh + ((size_t)(b*Sn + row)) * Dn + m0 + mm);
        }
        __syncthreads();

        #pragma unroll
        for (int mm = 0; mm < 32; mm += 4) {
            float4 wv = *(const float4*)&wq_sh[tloc][m0 + mm];
            float4 vv = *(const float4*)&v_sh[m0 + mm];
            float4 u0 = *(const float4*)&uh_sh[sbas     ][mm];
            float4 u1 = *(const float4*)&uh_sh[sbas + 32][mm];
            float4 u2 = *(const float4*)&uh_sh[sbas + 64][mm];
            a0 += tanh_fast(wv.x+u0.x)*vv.x; a0 += tanh_fast(wv.y+u0.y)*vv.y;
            a0 += tanh_fast(wv.z+u0.z)*vv.z; a0 += tanh_fast(wv.w+u0.w)*vv.w;
            a1 += tanh_fast(wv.x+u1.x)*vv.x; a1 += tanh_fast(wv.y+u1.y)*vv.y;
            a1 += tanh_fast(wv.z+u1.z)*vv.z; a1 += tanh_fast(wv.w+u1.w)*vv.w;
            a2 += tanh_fast(wv.x+u2.x)*vv.x; a2 += tanh_fast(wv.y+u2.y)*vv.y;
            a2 += tanh_fast(wv.z+u2.z)*vv.z; a2 += tanh_fast(wv.w+u2.w)*vv.w;
        }
    }

    const int L = lens[b];
    float vals[3] = {a0, a1, a2};
    float mx = -INFINITY;
    #pragma unroll
    for (int k = 0; k < 3; k++) {
        if (sbas + 32*k >= L) vals[k] = -INFINITY;
        mx = fmaxf(mx, vals[k]);
    }
    #pragma unroll
    for (int o = 16; o; o >>= 1) mx = fmaxf(mx, __shfl_xor_sync(0xFFFFFFFFu, mx, o));
    __syncthreads();
    if (lane == 0) rmax[w] = mx;
    __syncthreads();
    const float M = fmaxf(rmax[w], rmax[w ^ 1]);

    float sum = 0.f;
    #pragma unroll
    for (int k = 0; k < 3; k++) {
        float e = (vals[k] == -INFINITY) ? 0.f : __expf(vals[k] - M);
        vals[k] = e; sum += e;
    }
    #pragma unroll
    for (int o = 16; o; o >>= 1) sum += __shfl_xor_sync(0xFFFFFFFFu, sum, o);
    if (lane == 0) rsum[w] = sum;
    __syncthreads();
    const float inv = __fdividef(1.f, rsum[w] + rsum[w ^ 1]);

    const size_t rb = ((size_t)(b*Tn + t0 + tloc)) * Sn + sbas;
    #pragma unroll
    for (int k = 0; k < 3; k++) {
        float p = vals[k] * inv;
        P[rb + 32*k] = p;
        if (write_align) out_align[rb + 32*k] = p;
    }
}

// ----------------------------------------------------------------------------
// Stage 3: out = P @ Wm + base. 16x64 tile, 128 thr, 2x4 micro,
// DOUBLE-BUFFERED register prefetch: load(c+1) -> compute(c) -> STS -> 1 barrier.
// Grid (8, 6, 8) = 384 CTAs.
// ----------------------------------------------------------------------------
__global__ void __launch_bounds__(128) stage3_epilogue(
    const float* __restrict__ P, const float* __restrict__ Wm,
    const float* __restrict__ base, float* __restrict__ out)
{
    const int b  = blockIdx.z;
    const int m0 = blockIdx.y * 16;
    const int n0 = blockIdx.x * 64;
    const float* A  = P  + (size_t)b * Tn * Sn;
    const float* Bm = Wm + (size_t)b * Sn * Dn;

    __shared__ __align__(16) float As[2][16][20];
    __shared__ __align__(16) float Bs[2][16][68];

    const int tid = threadIdx.x;
    const int tm = tid >> 4;
    const int tn = tid & 15;
    const int am = tid >> 2, ak4 = (tid & 3) << 2;   // A-load mapping (tid<64)
    const int bkk = tid >> 4, bnn = (tid & 15) << 2; // B-load mapping

    float acc[2][4] = {};
    float4 aR, bR0, bR1;

    // load chunk 0 into regs, store to buf 0
    if (tid < 64) aR = *(const float4*)(A + (size_t)(m0 + am) * Sn + ak4);
    bR0 = *(const float4*)(Bm + (size_t)(bkk)     * Dn + n0 + bnn);
    bR1 = *(const float4*)(Bm + (size_t)(bkk + 8) * Dn + n0 + bnn);
    if (tid < 64) {
        As[0][ak4+0][am] = aR.x; As[0][ak4+1][am] = aR.y;
        As[0][ak4+2][am] = aR.z; As[0][ak4+3][am] = aR.w;
    }
    *(float4*)&Bs[0][bkk][bnn]     = bR0;
    *(float4*)&Bs[0][bkk + 8][bnn] = bR1;
    __syncthreads();

    for (int c = 0; c < 12; c++) {
        const int cur = c & 1;
        // prefetch next chunk into registers (hides under compute)
        if (c < 11) {
            const int k0 = (c + 1) * 16;
            if (tid < 64) aR = *(const float4*)(A + (size_t)(m0 + am) * Sn + k0 + ak4);
            bR0 = *(const float4*)(Bm + (size_t)(k0 + bkk)     * Dn + n0 + bnn);
            bR1 = *(const float4*)(Bm + (size_t)(k0 + bkk + 8) * Dn + n0 + bnn);
        }

        #pragma unroll
        for (int k = 0; k < 16; k++) {
            float a0 = As[cur][k][tm*2], a1 = As[cur][k][tm*2+1];
            float4 bv = *(const float4*)&Bs[cur][k][tn*4];
            acc[0][0] += a0*bv.x; acc[0][1] += a0*bv.y; acc[0][2] += a0*bv.z; acc[0][3] += a0*bv.w;
            acc[1][0] += a1*bv.x; acc[1][1] += a1*bv.y; acc[1][2] += a1*bv.z; acc[1][3] += a1*bv.w;
        }

        if (c < 11) {
            const int nxt = cur ^ 1;
            if (tid < 64) {
                As[nxt][ak4+0][am] = aR.x; As[nxt][ak4+1][am] = aR.y;
                As[nxt][ak4+2][am] = aR.z; As[nxt][ak4+3][am] = aR.w;
            }
            *(float4*)&Bs[nxt][bkk][bnn]     = bR0;
            *(float4*)&Bs[nxt][bkk + 8][bnn] = bR1;
        }
        __syncthreads();
    }

    #pragma unroll
    for (int i = 0; i < 2; i++) {
        const size_t r = (size_t)(b*Tn + m0 + tm*2 + i) * Dn + n0 + tn*4;
        float4 bb = *(const float4*)(base + r);
        float4 o;
        o.x = acc[i][0]+bb.x; o.y = acc[i][1]+bb.y;
        o.z = acc[i][2]+bb.z; o.w = acc[i][3]+bb.w;
        *(float4*)(out + r) = o;
    }
}

// ----------------------------------------------------------------------------
extern "C" void kernel_launch(void* const* d_in, const int* in_sizes, int n_in,
                              void* d_out, int out_size)
{
    const float* inputs = (const float*)d_in[0];
    const float* mems   = (const float*)d_in[1];
    const int*   lens   = (const int*)  d_in[2];
    const float* Wq     = (const float*)d_in[3];
    const float* Wc     = (const float*)d_in[4];
    const float* bc     = (const float*)d_in[5];
    const float* v      = (const float*)d_in[6];
    const float* Wout   = (const float*)d_in[7];
    const float* bout   = (const float*)d_in[8];
    float* out = (float*)d_out;

    float *wqb, *uhb, *wmb, *baseb, *pb;
    cudaGetSymbolAddress((void**)&wqb,   g_wq);
    cudaGetSymbolAddress((void**)&uhb,   g_uh);
    cudaGetSymbolAddress((void**)&wmb,   g_wm);
    cudaGetSymbolAddress((void**)&baseb, g_base);
    cudaGetSymbolAddress((void**)&pb,    g_p);

    __nv_bfloat16 *inh, *inl, *memh, *meml, *wqh, *wql, *wch, *wcl, *woh, *wol;
    cudaGetSymbolAddress((void**)&inh,  g_in_h);  cudaGetSymbolAddress((void**)&inl,  g_in_l);
    cudaGetSymbolAddress((void**)&memh, g_mem_h); cudaGetSymbolAddress((void**)&meml, g_mem_l);
    cudaGetSymbolAddress((void**)&wqh,  g_wqw_h); cudaGetSymbolAddress((void**)&wql,  g_wqw_l);
    cudaGetSymbolAddress((void**)&wch,  g_wcw_h); cudaGetSymbolAddress((void**)&wcl,  g_wcw_l);
    cudaGetSymbolAddress((void**)&woh,  g_wow_h); cudaGetSymbolAddress((void**)&wol,  g_wow_l);

    const int attn_elems  = BT * Dn;
    const int align_elems = BT * Sn;
    const int write_align = (out_size >= attn_elems + align_elems) ? 1 : 0;
    float* out_align = out + attn_elems;

    cudaFuncSetAttribute(stage1_mma, cudaFuncAttributeMaxDynamicSharedMemorySize, S1_SMEM);

    // 0) fp32 -> bf16 hi/lo pre-conversion
    preconvert<<<2176, 256>>>(
        (const float4*)inputs, (const float4*)mems,
        (const float4*)Wq, (const float4*)Wc, (const float4*)Wout,
        inh, inl, memh, meml, wqh, wql, wch, wcl, woh, wol);

    // 1) wq, uh, Wm, base — cp.async-staged mma.sync, 144 CTAs (one wave)
    stage1_mma<<<dim3(Dn/128, 36), 512, S1_SMEM>>>(
        inh, inl, memh, meml, wqh, wql, wch, wcl, woh, wol,
        bc, bout, wqb, uhb, wmb, baseb);

    // 2) score + masked softmax — 192 CTAs x 256 thr
    score_softmax<<<dim3(Tn/4, Bn), 256>>>(wqb, uhb, v, lens, pb, out_align, write_align);

    // 3) out = P @ Wm + base — 384 CTAs, pipelined
    stage3_epilogue<<<dim3(Dn/64, Tn/16, Bn), 128>>>(pb, wmb, baseb, out);
}

// round 15
// speedup vs baseline: 1.0620x; 1.0620x over previous
#include <cuda_runtime.h>
#include <cuda_bf16.h>
#include <math.h>
#include <cstdint>

#define Bn 8
#define Tn 96
#define Sn 192
#define Dn 512
#define BT (Bn*Tn)   // 768
#define BS (Bn*Sn)   // 1536

// Scratch
__device__ float g_wq  [BT * Dn];
__device__ float g_uh  [BS * Dn];
__device__ float g_wm  [BS * Dn];
__device__ float g_base[BT * Dn];
__device__ float g_p   [BT * Sn];

__device__ __forceinline__ float tanh_fast(float x) {
    float y;
    asm("tanh.approx.f32 %0, %1;" : "=f"(y) : "f"(x));
    return y;
}
__device__ __forceinline__ uint32_t smem_u32(const void* p) {
    uint32_t a;
    asm("{ .reg .u64 t; cvta.to.shared.u64 t, %1; cvt.u32.u64 %0, t; }" : "=r"(a) : "l"(p));
    return a;
}
__device__ __forceinline__ void ldsm4(uint32_t* r, uint32_t addr) {
    asm volatile("ldmatrix.sync.aligned.m8n8.x4.shared.b16 {%0,%1,%2,%3}, [%4];"
        : "=r"(r[0]), "=r"(r[1]), "=r"(r[2]), "=r"(r[3]) : "r"(addr));
}
__device__ __forceinline__ void ldsm2(uint32_t* r, uint32_t addr) {
    asm volatile("ldmatrix.sync.aligned.m8n8.x2.shared.b16 {%0,%1}, [%2];"
        : "=r"(r[0]), "=r"(r[1]) : "r"(addr));
}
__device__ __forceinline__ void mma16816(float* c, const uint32_t* a, const uint32_t* b) {
    asm volatile(
        "mma.sync.aligned.m16n8k16.row.col.f32.bf16.bf16.f32 "
        "{%0,%1,%2,%3}, {%4,%5,%6,%7}, {%8,%9}, {%0,%1,%2,%3};"
        : "+f"(c[0]), "+f"(c[1]), "+f"(c[2]), "+f"(c[3])
        : "r"(a[0]), "r"(a[1]), "r"(a[2]), "r"(a[3]), "r"(b[0]), "r"(b[1]));
}

// ----------------------------------------------------------------------------
// Stage 1 (R10 config): mma.sync bf16 hi/lo split, C = A @ W^T (+bias).
// CTA tile 128x128, 512 thr = 16 warps (4 M x 4 N), warp tile 32x32.
// K-chunk 32, double-buffered smem, register-prefetched LDG, inline convert.
// Grid (4, 36) = 144 CTAs = one wave.
// ----------------------------------------------------------------------------
#define PITCH 80
#define OAH 0
#define OAL 10240
#define OBH 20480
#define OBL 30720
#define BUFB 40960
#define S1_SMEM (2 * BUFB)   // 81920

__global__ void __launch_bounds__(512, 1) stage1_mma(
    const float* __restrict__ inputs, const float* __restrict__ mems,
    const float* __restrict__ Wq, const float* __restrict__ Wc,
    const float* __restrict__ bc, const float* __restrict__ Wout,
    const float* __restrict__ bout,
    float* __restrict__ wq_o, float* __restrict__ uh_o,
    float* __restrict__ wm_o, float* __restrict__ base_o)
{
    extern __shared__ __align__(16) unsigned char smem[];
    const uint32_t sb = smem_u32(smem);

    const int y = blockIdx.y;
    const float* A; const float* W; int ldw; const float* bias; float* C; int row0;
    if (y < 6)       { A = inputs; W = Wq;         ldw = 512;  bias = nullptr; C = wq_o;   row0 = y * 128; }
    else if (y < 18) { A = mems;   W = Wc;         ldw = 512;  bias = bc;      C = uh_o;   row0 = (y-6)*128; }
    else if (y < 30) { A = mems;   W = Wout;       ldw = 1024; bias = nullptr; C = wm_o;   row0 = (y-18)*128; }
    else             { A = inputs; W = Wout + 512; ldw = 1024; bias = bout;    C = base_o; row0 = (y-30)*128; }
    const int col0 = blockIdx.x * 128;

    const int tid  = threadIdx.x;
    const int wid  = tid >> 5;
    const int lane = tid & 31;
    const int wM   = wid >> 2;
    const int wN   = wid & 3;

    const int  crow  = (tid >> 1) & 127;
    const int  cisB  = tid >> 8;
    const int  chalf = tid & 1;
    const float4* csrc4 = (const float4*)((cisB ? (W + (size_t)(col0 + crow) * ldw)
                                                : (A + (size_t)(row0 + crow) * Dn))
                                          + chalf * 16);
    const int cvtOff = (cisB ? OBH : OAH) + crow * PITCH + chalf * 32;

    const uint32_t aOffA = (uint32_t)((wM * 32 + (lane & 15)) * PITCH + ((lane >> 4) << 4));
    const uint32_t aOffB = (uint32_t)((wN * 32 + (lane & 7)) * PITCH + (((lane >> 3) & 1) << 4));

    float acc[2][4][4];
    #pragma unroll
    for (int i = 0; i < 2; i++)
        #pragma unroll
        for (int j = 0; j < 4; j++)
            #pragma unroll
            for (int q = 0; q < 4; q++) acc[i][j][q] = 0.f;

    float4 pre[4];
    #pragma unroll
    for (int j = 0; j < 4; j++) pre[j] = csrc4[j];

    {
        unsigned char* sHi = smem + cvtOff;
        unsigned char* sLo = sHi + 10240;
        uint32_t hi[8], lo[8];
        #pragma unroll
        for (int j = 0; j < 4; j++) {
            float4 f = pre[j];
            __nv_bfloat162 h01 = __float22bfloat162_rn(make_float2(f.x, f.y));
            __nv_bfloat162 h23 = __float22bfloat162_rn(make_float2(f.z, f.w));
            float2 g01 = __bfloat1622float2(h01);
            float2 g23 = __bfloat1622float2(h23);
            __nv_bfloat162 l01 = __float22bfloat162_rn(make_float2(f.x - g01.x, f.y - g01.y));
            __nv_bfloat162 l23 = __float22bfloat162_rn(make_float2(f.z - g23.x, f.w - g23.y));
            hi[2*j]   = *(uint32_t*)&h01; hi[2*j+1] = *(uint32_t*)&h23;
            lo[2*j]   = *(uint32_t*)&l01; lo[2*j+1] = *(uint32_t*)&l23;
        }
        *(uint4*)(sHi)      = make_uint4(hi[0], hi[1], hi[2], hi[3]);
        *(uint4*)(sHi + 16) = make_uint4(hi[4], hi[5], hi[6], hi[7]);
        *(uint4*)(sLo)      = make_uint4(lo[0], lo[1], lo[2], lo[3]);
        *(uint4*)(sLo + 16) = make_uint4(lo[4], lo[5], lo[6], lo[7]);
    }
    __syncthreads();

    for (int c = 0; c < 16; c++) {
        const int cur = c & 1;
        const uint32_t bufc = sb + cur * BUFB;

        if (c < 15) {
            #pragma unroll
            for (int j = 0; j < 4; j++) pre[j] = csrc4[(c + 1) * 8 + j];
        }

        #pragma unroll
        for (int ks = 0; ks < 2; ks++) {
            const uint32_t kb = (uint32_t)(ks * 32);
            uint32_t Ah[2][4], Bh[4][2];
            #pragma unroll
            for (int mi = 0; mi < 2; mi++)
                ldsm4(Ah[mi], bufc + OAH + aOffA + mi * (16 * PITCH) + kb);
            #pragma unroll
            for (int ni = 0; ni < 4; ni++)
                ldsm2(Bh[ni], bufc + OBH + aOffB + ni * (8 * PITCH) + kb);
            #pragma unroll
            for (int mi = 0; mi < 2; mi++)
                #pragma unroll
                for (int ni = 0; ni < 4; ni++)
                    mma16816(acc[mi][ni], Ah[mi], Bh[ni]);

            uint32_t Al[2][4];
            #pragma unroll
            for (int mi = 0; mi < 2; mi++)
                ldsm4(Al[mi], bufc + OAL + aOffA + mi * (16 * PITCH) + kb);
            #pragma unroll
            for (int mi = 0; mi < 2; mi++)
                #pragma unroll
                for (int ni = 0; ni < 4; ni++)
                    mma16816(acc[mi][ni], Al[mi], Bh[ni]);

            uint32_t Bl[4][2];
            #pragma unroll
            for (int ni = 0; ni < 4; ni++)
                ldsm2(Bl[ni], bufc + OBL + aOffB + ni * (8 * PITCH) + kb);
            #pragma unroll
            for (int mi = 0; mi < 2; mi++)
                #pragma unroll
                for (int ni = 0; ni < 4; ni++)
                    mma16816(acc[mi][ni], Ah[mi], Bl[ni]);
        }

        if (c < 15) {
            unsigned char* sHi = smem + (cur ^ 1) * BUFB + cvtOff;
            unsigned char* sLo = sHi + 10240;
            uint32_t hi[8], lo[8];
            #pragma unroll
            for (int j = 0; j < 4; j++) {
                float4 f = pre[j];
                __nv_bfloat162 h01 = __float22bfloat162_rn(make_float2(f.x, f.y));
                __nv_bfloat162 h23 = __float22bfloat162_rn(make_float2(f.z, f.w));
                float2 g01 = __bfloat1622float2(h01);
                float2 g23 = __bfloat1622float2(h23);
                __nv_bfloat162 l01 = __float22bfloat162_rn(make_float2(f.x - g01.x, f.y - g01.y));
                __nv_bfloat162 l23 = __float22bfloat162_rn(make_float2(f.z - g23.x, f.w - g23.y));
                hi[2*j]   = *(uint32_t*)&h01; hi[2*j+1] = *(uint32_t*)&h23;
                lo[2*j]   = *(uint32_t*)&l01; lo[2*j+1] = *(uint32_t*)&l23;
            }
            *(uint4*)(sHi)      = make_uint4(hi[0], hi[1], hi[2], hi[3]);
            *(uint4*)(sHi + 16) = make_uint4(hi[4], hi[5], hi[6], hi[7]);
            *(uint4*)(sLo)      = make_uint4(lo[0], lo[1], lo[2], lo[3]);
            *(uint4*)(sLo + 16) = make_uint4(lo[4], lo[5], lo[6], lo[7]);
        }
        __syncthreads();
    }

    const int erow = lane >> 2;
    const int ecol = (lane & 3) * 2;
    #pragma unroll
    for (int mi = 0; mi < 2; mi++) {
        const int r0 = row0 + wM * 32 + mi * 16 + erow;
        #pragma unroll
        for (int ni = 0; ni < 4; ni++) {
            const int cc = col0 + wN * 32 + ni * 8 + ecol;
            float b0 = 0.f, b1 = 0.f;
            if (bias) { b0 = bias[cc]; b1 = bias[cc + 1]; }
            float2 o0 = make_float2(acc[mi][ni][0] + b0, acc[mi][ni][1] + b1);
            float2 o1 = make_float2(acc[mi][ni][2] + b0, acc[mi][ni][3] + b1);
            *(float2*)(C + (size_t)r0 * Dn + cc)       = o0;
            *(float2*)(C + (size_t)(r0 + 8) * Dn + cc) = o1;
        }
    }
}

// ----------------------------------------------------------------------------
// Stage 2: fused score + masked softmax (R10 version, 256 thr, static smem).
// ----------------------------------------------------------------------------
__global__ void __launch_bounds__(256) score_softmax(
    const float* __restrict__ wq, const float* __restrict__ uh,
    const float* __restrict__ v, const int* __restrict__ lens,
    float* __restrict__ P, float* __restrict__ out_align, int write_align)
{
    const int t0 = blockIdx.x * 4;
    const int b  = blockIdx.y;
    const int tid = threadIdx.x, w = tid >> 5, lane = tid & 31;
    const int tloc = w >> 1;
    const int sh   = w & 1;
    const int sbas = sh * 96 + lane;

    __shared__ __align__(16) float wq_sh[4][Dn];
    __shared__ __align__(16) float v_sh[Dn];
    __shared__ __align__(16) float uh_sh[Sn][36];
    __shared__ float rmax[8], rsum[8];

    for (int i = tid; i < 4 * (Dn/4); i += 256) {
        int t = i >> 7, j = i & 127;
        ((float4*)wq_sh[t])[j] = ((const float4*)(wq + ((size_t)(b*Tn + t0 + t)) * Dn))[j];
    }
    for (int i = tid; i < Dn/4; i += 256)
        ((float4*)v_sh)[i] = ((const float4*)v)[i];

    float a0=0.f, a1=0.f, a2=0.f;

    for (int m0 = 0; m0 < Dn; m0 += 32) {
        __syncthreads();
        #pragma unroll
        for (int i = tid; i < Sn * 8; i += 256) {
            int row = i >> 3, mm = (i & 7) << 2;
            *(float4*)&uh_sh[row][mm] =
                *(const float4*)(uh + ((size_t)(b*Sn + row)) * Dn + m0 + mm);
        }
        __syncthreads();

        #pragma unroll
        for (int mm = 0; mm < 32; mm += 4) {
            float4 wv = *(const float4*)&wq_sh[tloc][m0 + mm];
            float4 vv = *(const float4*)&v_sh[m0 + mm];
            float4 u0 = *(const float4*)&uh_sh[sbas     ][mm];
            float4 u1 = *(const float4*)&uh_sh[sbas + 32][mm];
            float4 u2 = *(const float4*)&uh_sh[sbas + 64][mm];
            a0 += tanh_fast(wv.x+u0.x)*vv.x; a0 += tanh_fast(wv.y+u0.y)*vv.y;
            a0 += tanh_fast(wv.z+u0.z)*vv.z; a0 += tanh_fast(wv.w+u0.w)*vv.w;
            a1 += tanh_fast(wv.x+u1.x)*vv.x; a1 += tanh_fast(wv.y+u1.y)*vv.y;
            a1 += tanh_fast(wv.z+u1.z)*vv.z; a1 += tanh_fast(wv.w+u1.w)*vv.w;
            a2 += tanh_fast(wv.x+u2.x)*vv.x; a2 += tanh_fast(wv.y+u2.y)*vv.y;
            a2 += tanh_fast(wv.z+u2.z)*vv.z; a2 += tanh_fast(wv.w+u2.w)*vv.w;
        }
    }

    const int L = lens[b];
    float vals[3] = {a0, a1, a2};
    float mx = -INFINITY;
    #pragma unroll
    for (int k = 0; k < 3; k++) {
        if (sbas + 32*k >= L) vals[k] = -INFINITY;
        mx = fmaxf(mx, vals[k]);
    }
    #pragma unroll
    for (int o = 16; o; o >>= 1) mx = fmaxf(mx, __shfl_xor_sync(0xFFFFFFFFu, mx, o));
    __syncthreads();
    if (lane == 0) rmax[w] = mx;
    __syncthreads();
    const float M = fmaxf(rmax[w], rmax[w ^ 1]);

    float sum = 0.f;
    #pragma unroll
    for (int k = 0; k < 3; k++) {
        float e = (vals[k] == -INFINITY) ? 0.f : __expf(vals[k] - M);
        vals[k] = e; sum += e;
    }
    #pragma unroll
    for (int o = 16; o; o >>= 1) sum += __shfl_xor_sync(0xFFFFFFFFu, sum, o);
    if (lane == 0) rsum[w] = sum;
    __syncthreads();
    const float inv = __fdividef(1.f, rsum[w] + rsum[w ^ 1]);

    const size_t rb = ((size_t)(b*Tn + t0 + tloc)) * Sn + sbas;
    #pragma unroll
    for (int k = 0; k < 3; k++) {
        float p = vals[k] * inv;
        P[rb + 32*k] = p;
        if (write_align) out_align[rb + 32*k] = p;
    }
}

// ----------------------------------------------------------------------------
// Stage 3 (R13 pipelined): out = P @ Wm + base. 16x64 tile, 128 thr,
// double-buffered register prefetch. Grid (8, 6, 8) = 384 CTAs.
// ----------------------------------------------------------------------------
__global__ void __launch_bounds__(128) stage3_epilogue(
    const float* __restrict__ P, const float* __restrict__ Wm,
    const float* __restrict__ base, float* __restrict__ out)
{
    const int b  = blockIdx.z;
    const int m0 = blockIdx.y * 16;
    const int n0 = blockIdx.x * 64;
    const float* A  = P  + (size_t)b * Tn * Sn;
    const float* Bm = Wm + (size_t)b * Sn * Dn;

    __shared__ __align__(16) float As[2][16][20];
    __shared__ __align__(16) float Bs[2][16][68];

    const int tid = threadIdx.x;
    const int tm = tid >> 4;
    const int tn = tid & 15;
    const int am = tid >> 2, ak4 = (tid & 3) << 2;
    const int bkk = tid >> 4, bnn = (tid & 15) << 2;

    float acc[2][4] = {};
    float4 aR, bR0, bR1;

    if (tid < 64) aR = *(const float4*)(A + (size_t)(m0 + am) * Sn + ak4);
    bR0 = *(const float4*)(Bm + (size_t)(bkk)     * Dn + n0 + bnn);
    bR1 = *(const float4*)(Bm + (size_t)(bkk + 8) * Dn + n0 + bnn);
    if (tid < 64) {
        As[0][ak4+0][am] = aR.x; As[0][ak4+1][am] = aR.y;
        As[0][ak4+2][am] = aR.z; As[0][ak4+3][am] = aR.w;
    }
    *(float4*)&Bs[0][bkk][bnn]     = bR0;
    *(float4*)&Bs[0][bkk + 8][bnn] = bR1;
    __syncthreads();

    for (int c = 0; c < 12; c++) {
        const int cur = c & 1;
        if (c < 11) {
            const int k0 = (c + 1) * 16;
            if (tid < 64) aR = *(const float4*)(A + (size_t)(m0 + am) * Sn + k0 + ak4);
            bR0 = *(const float4*)(Bm + (size_t)(k0 + bkk)     * Dn + n0 + bnn);
            bR1 = *(const float4*)(Bm + (size_t)(k0 + bkk + 8) * Dn + n0 + bnn);
        }

        #pragma unroll
        for (int k = 0; k < 16; k++) {
            float a0 = As[cur][k][tm*2], a1 = As[cur][k][tm*2+1];
            float4 bv = *(const float4*)&Bs[cur][k][tn*4];
            acc[0][0] += a0*bv.x; acc[0][1] += a0*bv.y; acc[0][2] += a0*bv.z; acc[0][3] += a0*bv.w;
            acc[1][0] += a1*bv.x; acc[1][1] += a1*bv.y; acc[1][2] += a1*bv.z; acc[1][3] += a1*bv.w;
        }

        if (c < 11) {
            const int nxt = cur ^ 1;
            if (tid < 64) {
                As[nxt][ak4+0][am] = aR.x; As[nxt][ak4+1][am] = aR.y;
                As[nxt][ak4+2][am] = aR.z; As[nxt][ak4+3][am] = aR.w;
            }
            *(float4*)&Bs[nxt][bkk][bnn]     = bR0;
            *(float4*)&Bs[nxt][bkk + 8][bnn] = bR1;
        }
        __syncthreads();
    }

    #pragma unroll
    for (int i = 0; i < 2; i++) {
        const size_t r = (size_t)(b*Tn + m0 + tm*2 + i) * Dn + n0 + tn*4;
        float4 bb = *(const float4*)(base + r);
        float4 o;
        o.x = acc[i][0]+bb.x; o.y = acc[i][1]+bb.y;
        o.z = acc[i][2]+bb.z; o.w = acc[i][3]+bb.w;
        *(float4*)(out + r) = o;
    }
}

// ----------------------------------------------------------------------------
extern "C" void kernel_launch(void* const* d_in, const int* in_sizes, int n_in,
                              void* d_out, int out_size)
{
    const float* inputs = (const float*)d_in[0];
    const float* mems   = (const float*)d_in[1];
    const int*   lens   = (const int*)  d_in[2];
    const float* Wq     = (const float*)d_in[3];
    const float* Wc     = (const float*)d_in[4];
    const float* bc     = (const float*)d_in[5];
    const float* v      = (const float*)d_in[6];
    const float* Wout   = (const float*)d_in[7];
    const float* bout   = (const float*)d_in[8];
    float* out = (float*)d_out;

    float *wqb, *uhb, *wmb, *baseb, *pb;
    cudaGetSymbolAddress((void**)&wqb,   g_wq);
    cudaGetSymbolAddress((void**)&uhb,   g_uh);
    cudaGetSymbolAddress((void**)&wmb,   g_wm);
    cudaGetSymbolAddress((void**)&baseb, g_base);
    cudaGetSymbolAddress((void**)&pb,    g_p);

    const int attn_elems  = BT * Dn;
    const int align_elems = BT * Sn;
    const int write_align = (out_size >= attn_elems + align_elems) ? 1 : 0;
    float* out_align = out + attn_elems;

    cudaFuncSetAttribute(stage1_mma, cudaFuncAttributeMaxDynamicSharedMemorySize, S1_SMEM);

    // 1) wq, uh, Wm, base — 512-thread pipelined mma.sync, 144 CTAs (one wave)
    stage1_mma<<<dim3(Dn/128, 36), 512, S1_SMEM>>>(
        inputs, mems, Wq, Wc, bc, Wout, bout, wqb, uhb, wmb, baseb);

    // 2) score + masked softmax — 192 CTAs x 256 thr
    score_softmax<<<dim3(Tn/4, Bn), 256>>>(wqb, uhb, v, lens, pb, out_align, write_align);

    // 3) out = P @ Wm + base — 384 CTAs, pipelined
    stage3_epilogue<<<dim3(Dn/64, Tn/16, Bn), 128>>>(pb, wmb, baseb, out);
}